// round 16
// baseline (speedup 1.0000x reference)
#include <cuda_runtime.h>
#include <cuda_fp16.h>
#include <cuda_bf16.h>

#define N_NODES 100000
#define E_MAX   640000
#define DIM     128
#define BIN_CAP 12        // 9.6 MB bins; P(deg>12 | lambda=6.4) ~ 1% -> overflow path

// Normalized feature cache, fp16: 25.6 MB.
__device__ uint4 g_hn[(size_t)N_NODES * DIM * 2 / 16];
// Per-node bins (touched bytes ~5 MB; untouched slots cost no L2 traffic).
__device__ int2 g_bin[(size_t)N_NODES * BIN_CAP];
__device__ int  g_bincnt[N_NODES];
// Overflow list (only ~3-6k entries ever touched).
__device__ int  g_ovfcnt;
__device__ int4 g_ovf[E_MAX];

// Kernel 1: TWO rows per warp, normalize -> fp16 cache. Zeroes counters.
__global__ void normalize_fp16_kernel(const float* __restrict__ h, int n) {
    int tid = blockIdx.x * blockDim.x + threadIdx.x;
    if (tid < N_NODES) g_bincnt[tid] = 0;
    if (tid == 0) g_ovfcnt = 0;

    int warp_id = tid >> 5;
    int lane = threadIdx.x & 31;
    int r0 = warp_id * 2;
    int r1 = r0 + 1;
    if (r0 >= n) return;
    bool has_r1 = (r1 < n);
    int r1c = has_r1 ? r1 : r0;

    const float4 v0 = __ldg(reinterpret_cast<const float4*>(h + (size_t)r0 * DIM) + lane);
    const float4 v1 = __ldg(reinterpret_cast<const float4*>(h + (size_t)r1c * DIM) + lane);

    float s0 = v0.x * v0.x + v0.y * v0.y + v0.z * v0.z + v0.w * v0.w;
    float s1 = v1.x * v1.x + v1.y * v1.y + v1.z * v1.z + v1.w * v1.w;
    #pragma unroll
    for (int off = 16; off > 0; off >>= 1) {
        s0 += __shfl_xor_sync(0xFFFFFFFFu, s0, off);
        s1 += __shfl_xor_sync(0xFFFFFFFFu, s1, off);
    }

    float inv0 = 1.0f / fmaxf(sqrtf(s0), 1e-12f);
    float inv1 = 1.0f / fmaxf(sqrtf(s1), 1e-12f);

    __half2 a0 = __floats2half2_rn(v0.x * inv0, v0.y * inv0);
    __half2 a1 = __floats2half2_rn(v0.z * inv0, v0.w * inv0);
    uint2 p0 = make_uint2(*reinterpret_cast<unsigned*>(&a0),
                          *reinterpret_cast<unsigned*>(&a1));
    reinterpret_cast<uint2*>(g_hn)[(size_t)r0 * 32 + lane] = p0;

    if (has_r1) {
        __half2 b0 = __floats2half2_rn(v1.x * inv1, v1.y * inv1);
        __half2 b1 = __floats2half2_rn(v1.z * inv1, v1.w * inv1);
        uint2 p1 = make_uint2(*reinterpret_cast<unsigned*>(&b0),
                              *reinterpret_cast<unsigned*>(&b1));
        reinterpret_cast<uint2*>(g_hn)[(size_t)r1 * 32 + lane] = p1;
    }
}

// Kernel 2: ONLY preprocessing pass. Bin slot order is nondeterministic but
// every edge is computed once with identical arithmetic -> values determinate.
__global__ void scatter_kernel(const int* __restrict__ src,
                               const int* __restrict__ dst, int e, int n) {
    int i = blockIdx.x * blockDim.x + threadIdx.x;
    if (i >= e) return;
    int nn = min(n, N_NODES);
    int s = min(max(__ldg(src + i), 0), nn - 1);
    int d = min(max(__ldg(dst + i), 0), nn - 1);
    int pos = atomicAdd(&g_bincnt[s], 1);
    if (pos < BIN_CAP) {
        g_bin[(size_t)s * BIN_CAP + pos] = make_int2(d, i);
    } else {
        int op = atomicAdd(&g_ovfcnt, 1);
        if (op < E_MAX) g_ovf[op] = make_int4(s, d, i, 0);
    }
}

// Dot of 8 fp16 pairs in two uint4's, fp32 accumulation.
__device__ __forceinline__ float dot8h(uint4 a, uint4 b) {
    float acc = 0.0f;
    #pragma unroll
    for (int w = 0; w < 4; w++) {
        unsigned ua = (&a.x)[w], ub = (&b.x)[w];
        __half2 ha = *reinterpret_cast<__half2*>(&ua);
        __half2 hb = *reinterpret_cast<__half2*>(&ub);
        float2 fa = __half22float2(ha);
        float2 fb = __half22float2(hb);
        acc = fmaf(fa.x, fb.x, acc);
        acc = fmaf(fa.y, fb.y, acc);
    }
    return acc;
}

// Kernel 3: one warp per node. Src row loaded once (4 groups issue identical
// addresses -> coalescer dedup). Up to 8 dst edges per iteration in two
// front-batched quad chains, 8 lanes per edge.
__global__ void __launch_bounds__(256)
sddmm_bin_kernel(float* __restrict__ out, int n) {
    int warp_id = (blockIdx.x * blockDim.x + threadIdx.x) >> 5;
    int lane = threadIdx.x & 31;
    if (warp_id >= n || warp_id >= N_NODES) return;
    int node = warp_id;

    int cnt = min(__ldg(g_bincnt + node), BIN_CAP);
    if (cnt == 0) return;

    int l = lane & 7;
    int g = lane >> 3;

    const uint4* row = g_hn + (size_t)node * 16;
    uint4 a_lo = __ldg(row + l);
    uint4 a_hi = __ldg(row + 8 + l);

    const int2* bin = g_bin + (size_t)node * BIN_CAP;

    for (int k0 = 0; k0 < cnt; k0 += 8) {
        int ka = k0 + g;
        int kb = k0 + 4 + g;
        bool va = (ka < cnt);
        bool vb = (kb < cnt);

        int2 pa = __ldg(bin + (va ? ka : 0));
        int2 pb = __ldg(bin + (vb ? kb : 0));

        const uint4* ra = g_hn + (size_t)pa.x * 16;
        const uint4* rb = g_hn + (size_t)pb.x * 16;

        uint4 b0lo = __ldg(ra + l);
        uint4 b0hi = __ldg(ra + 8 + l);
        uint4 b1lo = __ldg(rb + l);
        uint4 b1hi = __ldg(rb + 8 + l);

        float acc0 = dot8h(a_lo, b0lo) + dot8h(a_hi, b0hi);
        float acc1 = dot8h(a_lo, b1lo) + dot8h(a_hi, b1hi);

        #pragma unroll
        for (int off = 4; off > 0; off >>= 1) {
            acc0 += __shfl_xor_sync(0xFFFFFFFFu, acc0, off);
            acc1 += __shfl_xor_sync(0xFFFFFFFFu, acc1, off);
        }

        if (l == 0) {
            if (va) out[pa.y] = acc0;
            if (vb) out[pb.y] = acc1;
        }
    }
}

// Kernel 4: overflow cleanup. Fixed grid (graph capture forbids reading the
// count host-side); warps stride over the overflow list. One edge per warp,
// 16 active lanes.
#define OVF_WARPS 2048
__global__ void overflow_kernel(float* __restrict__ out) {
    int warp_id = (blockIdx.x * blockDim.x + threadIdx.x) >> 5;
    int lane = threadIdx.x & 31;
    int total = min(g_ovfcnt, E_MAX);

    for (int k = warp_id; k < total; k += OVF_WARPS) {
        int4 p = g_ovf[k];
        float acc = 0.0f;
        if (lane < 16) {
            uint4 a = __ldg(g_hn + (size_t)p.x * 16 + lane);
            uint4 b = __ldg(g_hn + (size_t)p.y * 16 + lane);
            acc = dot8h(a, b);
        }
        #pragma unroll
        for (int off = 8; off > 0; off >>= 1)
            acc += __shfl_xor_sync(0xFFFFFFFFu, acc, off);
        if (lane == 0)
            out[p.z] = acc;
    }
}

extern "C" void kernel_launch(void* const* d_in, const int* in_sizes, int n_in,
                              void* d_out, int out_size) {
    const float* h   = (const float*)d_in[0];
    const int*   src = (const int*)d_in[1];   // int32 (JAX demotes int64)
    const int*   dst = (const int*)d_in[2];
    float* out = (float*)d_out;

    int n = in_sizes[0] / DIM;     // 100000
    int e = in_sizes[1];           // 640000

    {   // K1: normalize + zero counters
        int warps = (n + 1) / 2;
        int blocks = (warps + 7) / 8;
        normalize_fp16_kernel<<<blocks, 256>>>(h, n);
    }
    {   // K2: scatter into fixed-capacity bins (the ONLY preprocessing pass)
        int blocks = (e + 255) / 256;
        scatter_kernel<<<blocks, 256>>>(src, dst, e, n);
    }
    {   // K3: one warp per node
        int blocks = (n + 7) / 8;
        sddmm_bin_kernel<<<blocks, 256>>>(out, n);
    }
    {   // K4: overflow edges (fixed grid, strided)
        overflow_kernel<<<OVF_WARPS / 8, 256>>>(out);
    }
}

// round 17
// speedup vs baseline: 2.3813x; 2.3813x over previous
#include <cuda_runtime.h>
#include <cuda_fp16.h>
#include <cuda_bf16.h>

#define N_NODES 100000
#define DIM 128

// Normalized feature cache, fp16: 100000 rows * 256 B = 25.6 MB.
__device__ uint4 g_hn[(size_t)N_NODES * DIM * 2 / 16];

// Kernel 1: FOUR rows per warp (MLP=4). Front-batched float4 loads, four
// interleaved butterfly reductions, four packed fp16 stores.
__global__ void normalize_fp16_kernel(const float* __restrict__ h, int n) {
    int warp_id = (blockIdx.x * blockDim.x + threadIdx.x) >> 5;
    int lane = threadIdx.x & 31;
    int r0 = warp_id * 4;
    if (r0 >= n) return;
    int r1 = min(r0 + 1, n - 1);
    int r2 = min(r0 + 2, n - 1);
    int r3 = min(r0 + 3, n - 1);
    bool h1 = (r0 + 1 < n), h2 = (r0 + 2 < n), h3 = (r0 + 3 < n);

    const float4 v0 = __ldg(reinterpret_cast<const float4*>(h + (size_t)r0 * DIM) + lane);
    const float4 v1 = __ldg(reinterpret_cast<const float4*>(h + (size_t)r1 * DIM) + lane);
    const float4 v2 = __ldg(reinterpret_cast<const float4*>(h + (size_t)r2 * DIM) + lane);
    const float4 v3 = __ldg(reinterpret_cast<const float4*>(h + (size_t)r3 * DIM) + lane);

    float s0 = v0.x * v0.x + v0.y * v0.y + v0.z * v0.z + v0.w * v0.w;
    float s1 = v1.x * v1.x + v1.y * v1.y + v1.z * v1.z + v1.w * v1.w;
    float s2 = v2.x * v2.x + v2.y * v2.y + v2.z * v2.z + v2.w * v2.w;
    float s3 = v3.x * v3.x + v3.y * v3.y + v3.z * v3.z + v3.w * v3.w;
    #pragma unroll
    for (int off = 16; off > 0; off >>= 1) {
        s0 += __shfl_xor_sync(0xFFFFFFFFu, s0, off);
        s1 += __shfl_xor_sync(0xFFFFFFFFu, s1, off);
        s2 += __shfl_xor_sync(0xFFFFFFFFu, s2, off);
        s3 += __shfl_xor_sync(0xFFFFFFFFu, s3, off);
    }

    float i0 = 1.0f / fmaxf(sqrtf(s0), 1e-12f);
    float i1 = 1.0f / fmaxf(sqrtf(s1), 1e-12f);
    float i2 = 1.0f / fmaxf(sqrtf(s2), 1e-12f);
    float i3 = 1.0f / fmaxf(sqrtf(s3), 1e-12f);

    uint2* outp = reinterpret_cast<uint2*>(g_hn);
    {
        __half2 a = __floats2half2_rn(v0.x * i0, v0.y * i0);
        __half2 b = __floats2half2_rn(v0.z * i0, v0.w * i0);
        outp[(size_t)r0 * 32 + lane] = make_uint2(*reinterpret_cast<unsigned*>(&a),
                                                  *reinterpret_cast<unsigned*>(&b));
    }
    if (h1) {
        __half2 a = __floats2half2_rn(v1.x * i1, v1.y * i1);
        __half2 b = __floats2half2_rn(v1.z * i1, v1.w * i1);
        outp[(size_t)r1 * 32 + lane] = make_uint2(*reinterpret_cast<unsigned*>(&a),
                                                  *reinterpret_cast<unsigned*>(&b));
    }
    if (h2) {
        __half2 a = __floats2half2_rn(v2.x * i2, v2.y * i2);
        __half2 b = __floats2half2_rn(v2.z * i2, v2.w * i2);
        outp[(size_t)r2 * 32 + lane] = make_uint2(*reinterpret_cast<unsigned*>(&a),
                                                  *reinterpret_cast<unsigned*>(&b));
    }
    if (h3) {
        __half2 a = __floats2half2_rn(v3.x * i3, v3.y * i3);
        __half2 b = __floats2half2_rn(v3.z * i3, v3.w * i3);
        outp[(size_t)r3 * 32 + lane] = make_uint2(*reinterpret_cast<unsigned*>(&a),
                                                  *reinterpret_cast<unsigned*>(&b));
    }
}

// Dot of 8 fp16 pairs in two uint4's, fp32 accumulation.
__device__ __forceinline__ float dot8h(uint4 a, uint4 b) {
    float acc = 0.0f;
    #pragma unroll
    for (int w = 0; w < 4; w++) {
        unsigned ua = (&a.x)[w], ub = (&b.x)[w];
        __half2 ha = *reinterpret_cast<__half2*>(&ua);
        __half2 hb = *reinterpret_cast<__half2*>(&ub);
        float2 fa = __half22float2(ha);
        float2 fb = __half22float2(hb);
        acc = fmaf(fa.x, fb.x, acc);
        acc = fmaf(fa.y, fb.y, acc);
    }
    return acc;
}

// Kernel 2 (round-12 WIN shape, unchanged): EIGHT edges per warp (two quads),
// 8 lanes/edge, 2 uint4/row/lane, all 8 row loads front-batched (MLP=8).
// Measured at the chip LTS cap (12.3 TB/s) -- do not touch.
__global__ void __launch_bounds__(256)
sddmm_cos_fp16_kernel(const int* __restrict__ src,
                      const int* __restrict__ dst,
                      float* __restrict__ out, int e, int n) {
    int warp_id = (blockIdx.x * blockDim.x + threadIdx.x) >> 5;
    int lane = threadIdx.x & 31;
    int g = lane >> 3;            // 0..3: edge within quad
    int l = lane & 7;             // 0..7: lane within edge

    int e0 = warp_id * 8 + g;     // quad 0
    int e1 = e0 + 4;              // quad 1
    if (e0 >= e) return;
    bool v1 = (e1 < e);
    int e1c = v1 ? e1 : e0;

    int s0 = min(max(__ldg(src + e0), 0), n - 1);
    int d0 = min(max(__ldg(dst + e0), 0), n - 1);
    int s1 = min(max(__ldg(src + e1c), 0), n - 1);
    int d1 = min(max(__ldg(dst + e1c), 0), n - 1);

    const uint4* sa0 = g_hn + (size_t)s0 * 16;
    const uint4* da0 = g_hn + (size_t)d0 * 16;
    const uint4* sa1 = g_hn + (size_t)s1 * 16;
    const uint4* da1 = g_hn + (size_t)d1 * 16;

    uint4 a0lo = __ldg(sa0 + l);
    uint4 a0hi = __ldg(sa0 + 8 + l);
    uint4 b0lo = __ldg(da0 + l);
    uint4 b0hi = __ldg(da0 + 8 + l);
    uint4 a1lo = __ldg(sa1 + l);
    uint4 a1hi = __ldg(sa1 + 8 + l);
    uint4 b1lo = __ldg(da1 + l);
    uint4 b1hi = __ldg(da1 + 8 + l);

    float acc0 = dot8h(a0lo, b0lo) + dot8h(a0hi, b0hi);
    float acc1 = dot8h(a1lo, b1lo) + dot8h(a1hi, b1hi);

    #pragma unroll
    for (int off = 4; off > 0; off >>= 1) {
        acc0 += __shfl_xor_sync(0xFFFFFFFFu, acc0, off);
        acc1 += __shfl_xor_sync(0xFFFFFFFFu, acc1, off);
    }

    if (l == 0) {
        out[e0] = acc0;
        if (v1) out[e1] = acc1;
    }
}

extern "C" void kernel_launch(void* const* d_in, const int* in_sizes, int n_in,
                              void* d_out, int out_size) {
    const float* h   = (const float*)d_in[0];
    const int*   src = (const int*)d_in[1];   // int32 (JAX demotes int64)
    const int*   dst = (const int*)d_in[2];
    float* out = (float*)d_out;

    int n = in_sizes[0] / DIM;     // 100000
    int e = in_sizes[1];           // 640000

    {   // Kernel 1: 4 rows/warp -> n/4 warps, 8 warps / 256-thread block
        int warps = (n + 3) / 4;
        int blocks = (warps + 7) / 8;
        normalize_fp16_kernel<<<blocks, 256>>>(h, n);
    }
    {   // Kernel 2: 8 edges/warp -> e/8 warps, 8 warps / block
        int warps = (e + 7) / 8;
        int blocks = (warps + 7) / 8;
        sddmm_cos_fp16_kernel<<<blocks, 256>>>(src, dst, out, e, n);
    }
}